// round 2
// baseline (speedup 1.0000x reference)
#include <cuda_runtime.h>
#include <cstdint>

typedef unsigned long long ull;

#define N_PTS 6000
#define N_TRI 16000
#define N_MOV 4000
#define N_BND 1500
#define BATCH 16
#define EPSF 1e-8f

// GEMM tiling
#define MPAD 4096
#define TSPLITS 20
#define TM 128
#define TCH 32
#define TRANGE 800            // per t-split: 20*800 = 16000
#define NCH (TRANGE/TCH)      // 25 chunks
#define VF_PITCH 36           // 32 + 4 pad floats (16B aligned, <=2-way bank conflicts)

// ------------------------- device scratch (no runtime alloc) -------------------------
__device__ double g_volc;
__device__ double g_vol[BATCH];
__device__ int    g_owner1[N_PTS];
__device__ int    g_owner2[N_PTS];
__device__ float  g_pz[BATCH * N_PTS * 3];
__device__ float2 g_D2[8 * N_TRI];                         // [bp][t], bp = batch pair
__device__ float  g_cpart[(size_t)TSPLITS * MPAD * BATCH]; // GEMM partials
__device__ float  g_c[BATCH * N_MOV];
__device__ float  g_s[BATCH];

// ------------------------- K1: init owners + zero volume accumulators -------------------------
__global__ void k_init() {
    int i = blockIdx.x * 256 + threadIdx.x;
    if (i < N_PTS) { g_owner1[i] = -1; g_owner2[i] = -1; }
    if (i == 0) g_volc = 0.0;
    if (i < BATCH) g_vol[i] = 0.0;
}

// ------------------------- K2: last-occurrence-wins owners -------------------------
__global__ void k_owners(const int* __restrict__ idx1, const int* __restrict__ idx2) {
    int i = blockIdx.x * 256 + threadIdx.x;
    if (i < N_MOV) atomicMax(&g_owner1[idx1[i]], i);
    if (i < N_BND) atomicMax(&g_owner2[idx2[i]], i);
}

// ------------------------- K3: build pz + copy pts=x into out -------------------------
__global__ void k_build(const float* __restrict__ x, const float* __restrict__ y,
                        const float* __restrict__ pz0, float* __restrict__ out) {
    int i = blockIdx.x * 256 + threadIdx.x;
    if (i < BATCH * N_PTS) {
        int b = i / N_PTS, p = i - b * N_PTS;
        float cx = pz0[p * 3 + 0], cy = pz0[p * 3 + 1], cz = pz0[p * 3 + 2];
        int o2 = g_owner2[p];
        if (o2 >= 0) {
            cx = y[b * (2 * N_BND) + o2 * 2 + 0];
            cz = y[b * (2 * N_BND) + o2 * 2 + 1];
        }
        int o1 = g_owner1[p];
        if (o1 >= 0) {
            cx = x[(b * N_MOV + o1) * 3 + 0];
            cy = x[(b * N_MOV + o1) * 3 + 1];
            cz = x[(b * N_MOV + o1) * 3 + 2];
        }
        g_pz[i * 3 + 0] = cx; g_pz[i * 3 + 1] = cy; g_pz[i * 3 + 2] = cz;
    }
    // pts = x  (out is poisoned 0xAA before timing; we must fully write it)
    int stride = gridDim.x * 256;
    for (int j = i; j < BATCH * N_MOV * 3; j += stride) out[j] = x[j];
}

// ------------------------- K4: volumes (vol_const at b==BATCH, vol(pz) per b) -------------------------
__global__ void k_vol(const float* __restrict__ pz0, const int* __restrict__ tri) {
    __shared__ double sred[256];
    int t = blockIdx.x * 256 + threadIdx.x;
    int b = blockIdx.y;
    const float* P = (b < BATCH) ? (g_pz + (size_t)b * N_PTS * 3) : pz0;
    double contrib = 0.0;
    if (t < N_TRI) {
        int p0 = tri[3 * t + 0] * 3, p1 = tri[3 * t + 1] * 3, p2 = tri[3 * t + 2] * 3;
        float x0 = P[p0], y0 = P[p0 + 1], z0 = P[p0 + 2];
        float x1 = P[p1], y1 = P[p1 + 1], z1 = P[p1 + 2];
        float x2 = P[p2], y2 = P[p2 + 1], z2 = P[p2 + 2];
        float det = (y1 - y0) * (z2 - z0) - (z1 - z0) * (y2 - y0);
        contrib = (double)((x0 + x1 + x2) * (det * (1.0f / 6.0f)));
    }
    sred[threadIdx.x] = contrib;
    __syncthreads();
    for (int o = 128; o > 0; o >>= 1) {
        if (threadIdx.x < o) sred[threadIdx.x] += sred[threadIdx.x + o];
        __syncthreads();
    }
    if (threadIdx.x == 0) {
        if (b < BATCH) atomicAdd(&g_vol[b], sred[0]);
        else           atomicAdd(&g_volc, sred[0]);
    }
}

// ------------------------- K5: per-triangle coefficient dets, packed [bp][t] float2 -------------------------
template <int AXIS>
__global__ void k_det(const int* __restrict__ tri) {
    int i = blockIdx.x * 256 + threadIdx.x;
    if (i >= 8 * N_TRI) return;
    int bp = i / N_TRI;
    int t  = i - bp * N_TRI;
    int p0 = tri[3 * t + 0] * 3, p1 = tri[3 * t + 1] * 3, p2 = tri[3 * t + 2] * 3;
    float2 r;
#pragma unroll
    for (int h = 0; h < 2; h++) {
        const float* P = g_pz + (size_t)(bp * 2 + h) * N_PTS * 3;
        float det;
        if (AXIS == 2) {       // coeff_z: uses (x,y), pivot vertex 2
            float x0 = P[p0], y0 = P[p0 + 1], x1 = P[p1], y1 = P[p1 + 1], x2 = P[p2], y2 = P[p2 + 1];
            det = (x0 - x2) * (y1 - y2) - (y0 - y2) * (x1 - x2);
        } else if (AXIS == 1) { // coeff_y: uses (x,z), pivot vertex 1
            float x0 = P[p0], z0 = P[p0 + 2], x1 = P[p1], z1 = P[p1 + 2], x2 = P[p2], z2 = P[p2 + 2];
            det = (x0 - x1) * (z2 - z1) - (z0 - z1) * (x2 - x1);
        } else {               // coeff_x: uses (y,z), pivot vertex 0
            float y0 = P[p0 + 1], z0 = P[p0 + 2], y1 = P[p1 + 1], z1 = P[p1 + 2], y2 = P[p2 + 1], z2 = P[p2 + 2];
            det = (y1 - y0) * (z2 - z0) - (z1 - z0) * (y2 - y0);
        }
        float v = det * (1.0f / 6.0f);
        if (h == 0) r.x = v; else r.y = v;
    }
    g_D2[i] = r;
}

// ------------------------- K6: c[m][b] = sum_t Vf[m][t] * d[b][t]  (HBM-bound pass over Vf) -------------------------
__device__ __forceinline__ void cp16(void* dst, const void* src) {
    unsigned d = (unsigned)__cvta_generic_to_shared(dst);
    asm volatile("cp.async.cg.shared.global [%0], [%1], 16;" :: "r"(d), "l"(src));
}

__global__ void __launch_bounds__(256, 2) k_gemm(const float* __restrict__ Vf) {
    __shared__ float  sVf[2][TM * VF_PITCH];  // 36864 B
    __shared__ float2 sD[2][8 * TCH];         //  4096 B
    const int tid   = threadIdx.x;
    const int mbase = blockIdx.x * TM;
    const int s     = blockIdx.y;
    const int tbase = s * TRANGE;

    auto load_stage = [&](int st, int tb) {
#pragma unroll
        for (int k = 0; k < 4; k++) {
            int q = tid + 256 * k;
            int r = q >> 3, seg = q & 7;
            int m = mbase + r;
            if (m < N_MOV)
                cp16(&sVf[st][r * VF_PITCH + seg * 4], Vf + (size_t)m * N_TRI + tb + seg * 4);
        }
        if (tid < 128) {
            int bp = tid >> 4, seg = tid & 15;
            cp16((char*)&sD[st][bp * TCH] + seg * 16,
                 (const char*)(g_D2 + (size_t)bp * N_TRI + tb) + seg * 16);
        }
        asm volatile("cp.async.commit_group;" ::: "memory");
    };

    ull acc[4][8];
#pragma unroll
    for (int i = 0; i < 4; i++)
#pragma unroll
        for (int bp = 0; bp < 8; bp++) acc[i][bp] = 0ull;

    load_stage(0, tbase);
    load_stage(1, tbase + TCH);

    const int mg   = tid >> 3;  // 0..31 : owns m = mbase + mg*4 + i
    const int tsub = tid & 7;   // 0..7  : owns t = tsub + 8*j in each chunk

    for (int c = 0; c < NCH; c++) {
        asm volatile("cp.async.wait_group 1;" ::: "memory");
        __syncthreads();
        const int st = c & 1;
#pragma unroll
        for (int j = 0; j < 4; j++) {
            const int t = tsub + 8 * j;
            ull dv[8];
#pragma unroll
            for (int bp = 0; bp < 8; bp++)
                dv[bp] = *reinterpret_cast<const ull*>(&sD[st][bp * TCH + t]);
#pragma unroll
            for (int i = 0; i < 4; i++) {
                unsigned vu = __float_as_uint(sVf[st][(mg * 4 + i) * VF_PITCH + t]);
                ull v2;
                asm("mov.b64 %0, {%1,%1};" : "=l"(v2) : "r"(vu));
#pragma unroll
                for (int bp = 0; bp < 8; bp++)
                    asm("fma.rn.f32x2 %0, %1, %2, %0;" : "+l"(acc[i][bp]) : "l"(v2), "l"(dv[bp]));
            }
        }
        __syncthreads();
        if (c + 2 < NCH) load_stage(st, tbase + (c + 2) * TCH);
        else asm volatile("cp.async.commit_group;" ::: "memory");
    }

    // deterministic butterfly reduce over the 8 t-sublanes (contiguous lanes in-warp)
#pragma unroll
    for (int i = 0; i < 4; i++) {
#pragma unroll
        for (int bp = 0; bp < 8; bp++) {
            float lo = __uint_as_float((unsigned)(acc[i][bp] & 0xffffffffull));
            float hi = __uint_as_float((unsigned)(acc[i][bp] >> 32));
#pragma unroll
            for (int d = 1; d < 8; d <<= 1) {
                lo += __shfl_xor_sync(0xffffffffu, lo, d);
                hi += __shfl_xor_sync(0xffffffffu, hi, d);
            }
            if (tsub == 0) {
                int m = mbase + mg * 4 + i;
                float* dst = &g_cpart[((size_t)s * MPAD + m) * BATCH];
                dst[2 * bp + 0] = lo;
                dst[2 * bp + 1] = hi;
            }
        }
    }
}

// ------------------------- K7: finalize c, compute per-batch scale -------------------------
__global__ void k_scale() {
    __shared__ float red[256];
    int b = blockIdx.x;
    int tid = threadIdx.x;
    float sq = 0.f;
    for (int m = tid; m < N_MOV; m += 256) {
        float cv = 0.f;
#pragma unroll
        for (int sp = 0; sp < TSPLITS; sp++)
            cv += g_cpart[((size_t)sp * MPAD + m) * BATCH + b];
        g_c[b * N_MOV + m] = cv;
        sq += cv * cv;
    }
    red[tid] = sq;
    __syncthreads();
    for (int o = 128; o > 0; o >>= 1) {
        if (tid < o) red[tid] += red[tid + o];
        __syncthreads();
    }
    if (tid == 0) {
        float a = (float)((g_volc - g_vol[b]) / 3.0);
        g_s[b] = a / (red[0] + EPSF);
    }
}

// ------------------------- K8: pts[:,:,axis] += d ; pz[:,indices_1,axis] = pts (winner) -------------------------
__global__ void k_update(const int* __restrict__ idx1, float* __restrict__ out, int axis) {
    int i = blockIdx.x * 256 + threadIdx.x;
    if (i >= BATCH * N_MOV) return;
    int b = i / N_MOV;
    int m = i - b * N_MOV;
    float nv = out[i * 3 + axis] + g_c[i] * g_s[b];
    out[i * 3 + axis] = nv;
    int p = idx1[m];
    if (g_owner1[p] == m) g_pz[((size_t)b * N_PTS + p) * 3 + axis] = nv;
}

// ------------------------- host -------------------------
extern "C" void kernel_launch(void* const* d_in, const int* in_sizes, int n_in,
                              void* d_out, int out_size) {
    const float* x   = (const float*)d_in[0];
    const float* y   = (const float*)d_in[1];
    const float* pz0 = (const float*)d_in[2];
    const float* Vf  = (const float*)d_in[3];
    const int* idx1  = (const int*)d_in[4];
    const int* idx2  = (const int*)d_in[5];
    const int* tri   = (const int*)d_in[6];
    float* out = (float*)d_out;

    k_init<<<24, 256>>>();
    k_owners<<<16, 256>>>(idx1, idx2);
    k_build<<<375, 256>>>(x, y, pz0, out);
    k_vol<<<dim3(63, BATCH + 1), 256>>>(pz0, tri);

    // axis 2 (coeff_z), axis 1 (coeff_y), axis 0 (coeff_x) — sequentially dependent
    k_det<2><<<500, 256>>>(tri);
    k_gemm<<<dim3(32, TSPLITS), 256>>>(Vf);
    k_scale<<<BATCH, 256>>>();
    k_update<<<250, 256>>>(idx1, out, 2);

    k_det<1><<<500, 256>>>(tri);
    k_gemm<<<dim3(32, TSPLITS), 256>>>(Vf);
    k_scale<<<BATCH, 256>>>();
    k_update<<<250, 256>>>(idx1, out, 1);

    k_det<0><<<500, 256>>>(tri);
    k_gemm<<<dim3(32, TSPLITS), 256>>>(Vf);
    k_scale<<<BATCH, 256>>>();
    k_update<<<250, 256>>>(idx1, out, 0);
}

// round 3
// speedup vs baseline: 1.2817x; 1.2817x over previous
#include <cuda_runtime.h>
#include <cstdint>

typedef unsigned long long ull;

#define N_PTS 6000
#define N_TRI 16000
#define N_MOV 4000
#define N_BND 1500
#define BATCH 16
#define EPSF 1e-8f

// GEMM v2 tiling
#define TW 128              // t per iteration
#define NITER (N_TRI / TW)  // 125
#define TSPLITS 7
#define MTILES 63           // ceil(4000/64)
#define SMEM_BYTES 81920    // 2*8192 Vf + 2*1024 lo + 2*1024 hi floats

// ------------------------- device scratch (no runtime alloc) -------------------------
__device__ double g_volc;
__device__ double g_vol[BATCH];
__device__ int    g_owner1[N_PTS];
__device__ int    g_owner2[N_PTS];
__device__ float  g_pz[BATCH * N_PTS * 3];
__device__ float  g_Dlo[8 * N_TRI];   // batch 2*bp
__device__ float  g_Dhi[8 * N_TRI];   // batch 2*bp+1
__device__ float  g_cpart[(size_t)TSPLITS * 4032 * 16];  // [ts][m(4032 pad)][b]
__device__ float  g_c[BATCH * N_MOV];
__device__ float  g_s[BATCH];

// ------------------------- K1: init owners + zero volume accumulators -------------------------
__global__ void k_init() {
    int i = blockIdx.x * 256 + threadIdx.x;
    if (i < N_PTS) { g_owner1[i] = -1; g_owner2[i] = -1; }
    if (i == 0) g_volc = 0.0;
    if (i < BATCH) g_vol[i] = 0.0;
}

// ------------------------- K2: last-occurrence-wins owners -------------------------
__global__ void k_owners(const int* __restrict__ idx1, const int* __restrict__ idx2) {
    int i = blockIdx.x * 256 + threadIdx.x;
    if (i < N_MOV) atomicMax(&g_owner1[idx1[i]], i);
    if (i < N_BND) atomicMax(&g_owner2[idx2[i]], i);
}

// ------------------------- K3: build pz + copy pts=x into out -------------------------
__global__ void k_build(const float* __restrict__ x, const float* __restrict__ y,
                        const float* __restrict__ pz0, float* __restrict__ out) {
    int i = blockIdx.x * 256 + threadIdx.x;
    if (i < BATCH * N_PTS) {
        int b = i / N_PTS, p = i - b * N_PTS;
        float cx = pz0[p * 3 + 0], cy = pz0[p * 3 + 1], cz = pz0[p * 3 + 2];
        int o2 = g_owner2[p];
        if (o2 >= 0) {
            cx = y[b * (2 * N_BND) + o2 * 2 + 0];
            cz = y[b * (2 * N_BND) + o2 * 2 + 1];
        }
        int o1 = g_owner1[p];
        if (o1 >= 0) {
            cx = x[(b * N_MOV + o1) * 3 + 0];
            cy = x[(b * N_MOV + o1) * 3 + 1];
            cz = x[(b * N_MOV + o1) * 3 + 2];
        }
        g_pz[i * 3 + 0] = cx; g_pz[i * 3 + 1] = cy; g_pz[i * 3 + 2] = cz;
    }
    int stride = gridDim.x * 256;
    for (int j = i; j < BATCH * N_MOV * 3; j += stride) out[j] = x[j];
}

// ------------------------- K4: volumes (vol_const at b==BATCH, vol(pz) per b) -------------------------
__global__ void k_vol(const float* __restrict__ pz0, const int* __restrict__ tri) {
    __shared__ double sred[256];
    int t = blockIdx.x * 256 + threadIdx.x;
    int b = blockIdx.y;
    const float* P = (b < BATCH) ? (g_pz + (size_t)b * N_PTS * 3) : pz0;
    double contrib = 0.0;
    if (t < N_TRI) {
        int p0 = tri[3 * t + 0] * 3, p1 = tri[3 * t + 1] * 3, p2 = tri[3 * t + 2] * 3;
        float x0 = P[p0], y0 = P[p0 + 1], z0 = P[p0 + 2];
        float x1 = P[p1], y1 = P[p1 + 1], z1 = P[p1 + 2];
        float x2 = P[p2], y2 = P[p2 + 1], z2 = P[p2 + 2];
        float det = (y1 - y0) * (z2 - z0) - (z1 - z0) * (y2 - y0);
        contrib = (double)((x0 + x1 + x2) * (det * (1.0f / 6.0f)));
    }
    sred[threadIdx.x] = contrib;
    __syncthreads();
    for (int o = 128; o > 0; o >>= 1) {
        if (threadIdx.x < o) sred[threadIdx.x] += sred[threadIdx.x + o];
        __syncthreads();
    }
    if (threadIdx.x == 0) {
        if (b < BATCH) atomicAdd(&g_vol[b], sred[0]);
        else           atomicAdd(&g_volc, sred[0]);
    }
}

// ------------------------- K5: per-triangle coefficient dets -> SoA lo/hi planes -------------------------
template <int AXIS>
__global__ void k_det(const int* __restrict__ tri) {
    int i = blockIdx.x * 256 + threadIdx.x;
    if (i >= 8 * N_TRI) return;
    int bp = i / N_TRI;
    int t  = i - bp * N_TRI;
    int p0 = tri[3 * t + 0] * 3, p1 = tri[3 * t + 1] * 3, p2 = tri[3 * t + 2] * 3;
#pragma unroll
    for (int h = 0; h < 2; h++) {
        const float* P = g_pz + (size_t)(bp * 2 + h) * N_PTS * 3;
        float det;
        if (AXIS == 2) {       // coeff_z: uses (x,y), pivot vertex 2
            float x0 = P[p0], y0 = P[p0 + 1], x1 = P[p1], y1 = P[p1 + 1], x2 = P[p2], y2 = P[p2 + 1];
            det = (x0 - x2) * (y1 - y2) - (y0 - y2) * (x1 - x2);
        } else if (AXIS == 1) { // coeff_y: uses (x,z), pivot vertex 1
            float x0 = P[p0], z0 = P[p0 + 2], x1 = P[p1], z1 = P[p1 + 2], x2 = P[p2], z2 = P[p2 + 2];
            det = (x0 - x1) * (z2 - z1) - (z0 - z1) * (x2 - x1);
        } else {               // coeff_x: uses (y,z), pivot vertex 0
            float y0 = P[p0 + 1], z0 = P[p0 + 2], y1 = P[p1 + 1], z1 = P[p1 + 2], y2 = P[p2 + 1], z2 = P[p2 + 2];
            det = (y1 - y0) * (z2 - z0) - (z1 - z0) * (y2 - y0);
        }
        float v = det * (1.0f / 6.0f);
        if (h == 0) g_Dlo[i] = v; else g_Dhi[i] = v;
    }
}

// ------------------------- K6: c[m][b] = sum_t Vf[m][t] * d[b][t] -------------------------
__device__ __forceinline__ void cp16(void* dst, const void* src) {
    unsigned d = (unsigned)__cvta_generic_to_shared(dst);
    asm volatile("cp.async.cg.shared.global [%0], [%1], 16;" :: "r"(d), "l"(src));
}

__global__ void __launch_bounds__(256, 1) k_gemm(const float* __restrict__ Vf) {
    extern __shared__ float sm[];
    float* sVf = sm;            // [2][64*128]
    float* sLo = sm + 16384;    // [2][8*128]
    float* sHi = sm + 18432;    // [2][8*128]

    const int tid  = threadIdx.x;
    const int lane = tid & 31;
    const int w    = tid >> 5;              // 0..7, warp owns 8 m-rows
    const int mbase = blockIdx.x * 64;
    const int by   = blockIdx.y;
    const int it0  = (NITER * by) / TSPLITS;
    const int it1  = (NITER * (by + 1)) / TSPLITS;

    auto load_stage = [&](int st, int it) {
        const int t0 = it * TW;
#pragma unroll
        for (int k = 0; k < 8; k++) {       // Vf: 64 rows x 512B
            int q = k * 256 + tid;
            int r = q >> 5, seg = q & 31;
            if (mbase + r < N_MOV)
                cp16(&sVf[st * 8192 + r * TW + seg * 4],
                     Vf + (size_t)(mbase + r) * N_TRI + t0 + seg * 4);
        }
        {                                   // d: 8 rows x 512B, lo + hi
            int r = tid >> 5, seg = tid & 31;
            cp16(&sLo[st * 1024 + r * TW + seg * 4], g_Dlo + r * N_TRI + t0 + seg * 4);
            cp16(&sHi[st * 1024 + r * TW + seg * 4], g_Dhi + r * N_TRI + t0 + seg * 4);
        }
        asm volatile("cp.async.commit_group;" ::: "memory");
    };

    ull acc[8][8];
#pragma unroll
    for (int i = 0; i < 8; i++)
#pragma unroll
        for (int bp = 0; bp < 8; bp++) acc[i][bp] = 0ull;

    load_stage(0, it0);
    if (it0 + 1 < it1) load_stage(1, it0 + 1);
    else asm volatile("cp.async.commit_group;" ::: "memory");

    for (int it = it0; it < it1; ++it) {
        const int st = (it - it0) & 1;
        asm volatile("cp.async.wait_group 1;" ::: "memory");
        __syncthreads();

        const float* vb  = sVf + st * 8192 + w * 8 * TW;
        const float* plo = sLo + st * 1024;
        const float* phi = sHi + st * 1024;
#pragma unroll
        for (int tq = 0; tq < 4; tq++) {
            const int t = lane + 32 * tq;   // stride-32 lanes: conflict-free LDS
            ull dv[8];
#pragma unroll
            for (int bp = 0; bp < 8; bp++) {
                float l = plo[bp * TW + t];
                float h = phi[bp * TW + t];
                asm("mov.b64 %0, {%1,%2};" : "=l"(dv[bp]) : "f"(l), "f"(h));
            }
#pragma unroll
            for (int i = 0; i < 8; i++) {
                float f = vb[i * TW + t];
                ull v2; asm("mov.b64 %0, {%1,%1};" : "=l"(v2) : "f"(f));
#pragma unroll
                for (int bp = 0; bp < 8; bp++)
                    asm("fma.rn.f32x2 %0, %1, %2, %0;" : "+l"(acc[i][bp]) : "l"(v2), "l"(dv[bp]));
            }
        }
        __syncthreads();
        if (it + 2 < it1) load_stage(st, it + 2);
        else asm volatile("cp.async.commit_group;" ::: "memory");
    }

    // deterministic 32-lane butterfly reduce, lane0 stores partials
#pragma unroll
    for (int i = 0; i < 8; i++) {
        const int m = mbase + w * 8 + i;
#pragma unroll
        for (int bp = 0; bp < 8; bp++) {
            float lo = __uint_as_float((unsigned)(acc[i][bp] & 0xffffffffull));
            float hi = __uint_as_float((unsigned)(acc[i][bp] >> 32));
#pragma unroll
            for (int d = 1; d < 32; d <<= 1) {
                lo += __shfl_xor_sync(0xffffffffu, lo, d);
                hi += __shfl_xor_sync(0xffffffffu, hi, d);
            }
            if (lane == 0 && m < N_MOV) {
                float* dst = &g_cpart[((size_t)by * 4032 + m) * 16];
                dst[2 * bp + 0] = lo;
                dst[2 * bp + 1] = hi;
            }
        }
    }
}

// ------------------------- K7: finalize c, compute per-batch scale -------------------------
__global__ void k_scale() {
    __shared__ float red[256];
    int b = blockIdx.x;
    int tid = threadIdx.x;
    float sq = 0.f;
    for (int m = tid; m < N_MOV; m += 256) {
        float cv = 0.f;
#pragma unroll
        for (int sp = 0; sp < TSPLITS; sp++)
            cv += g_cpart[((size_t)sp * 4032 + m) * 16 + b];
        g_c[b * N_MOV + m] = cv;
        sq += cv * cv;
    }
    red[tid] = sq;
    __syncthreads();
    for (int o = 128; o > 0; o >>= 1) {
        if (tid < o) red[tid] += red[tid + o];
        __syncthreads();
    }
    if (tid == 0) {
        float a = (float)((g_volc - g_vol[b]) / 3.0);
        g_s[b] = a / (red[0] + EPSF);
    }
}

// ------------------------- K8: pts[:,:,axis] += d ; pz[:,indices_1,axis] = pts (winner) -------------------------
__global__ void k_update(const int* __restrict__ idx1, float* __restrict__ out, int axis) {
    int i = blockIdx.x * 256 + threadIdx.x;
    if (i >= BATCH * N_MOV) return;
    int b = i / N_MOV;
    int m = i - b * N_MOV;
    float nv = out[i * 3 + axis] + g_c[i] * g_s[b];
    out[i * 3 + axis] = nv;
    int p = idx1[m];
    if (g_owner1[p] == m) g_pz[((size_t)b * N_PTS + p) * 3 + axis] = nv;
}

// ------------------------- host -------------------------
extern "C" void kernel_launch(void* const* d_in, const int* in_sizes, int n_in,
                              void* d_out, int out_size) {
    const float* x   = (const float*)d_in[0];
    const float* y   = (const float*)d_in[1];
    const float* pz0 = (const float*)d_in[2];
    const float* Vf  = (const float*)d_in[3];
    const int* idx1  = (const int*)d_in[4];
    const int* idx2  = (const int*)d_in[5];
    const int* tri   = (const int*)d_in[6];
    float* out = (float*)d_out;

    static bool attr_set = false;   // idempotent attribute, not state affecting results
    if (!attr_set) {
        cudaFuncSetAttribute(k_gemm, cudaFuncAttributeMaxDynamicSharedMemorySize, SMEM_BYTES);
        attr_set = true;
    }

    k_init<<<24, 256>>>();
    k_owners<<<16, 256>>>(idx1, idx2);
    k_build<<<375, 256>>>(x, y, pz0, out);
    k_vol<<<dim3(63, BATCH + 1), 256>>>(pz0, tri);

    // axis 2 (coeff_z), axis 1 (coeff_y), axis 0 (coeff_x) — sequentially dependent
    k_det<2><<<500, 256>>>(tri);
    k_gemm<<<dim3(MTILES, TSPLITS), 256, SMEM_BYTES>>>(Vf);
    k_scale<<<BATCH, 256>>>();
    k_update<<<250, 256>>>(idx1, out, 2);

    k_det<1><<<500, 256>>>(tri);
    k_gemm<<<dim3(MTILES, TSPLITS), 256, SMEM_BYTES>>>(Vf);
    k_scale<<<BATCH, 256>>>();
    k_update<<<250, 256>>>(idx1, out, 1);

    k_det<0><<<500, 256>>>(tri);
    k_gemm<<<dim3(MTILES, TSPLITS), 256, SMEM_BYTES>>>(Vf);
    k_scale<<<BATCH, 256>>>();
    k_update<<<250, 256>>>(idx1, out, 0);
}

// round 5
// speedup vs baseline: 1.5295x; 1.1933x over previous
#include <cuda_runtime.h>
#include <cuda_bf16.h>
#include <cstdint>

#define N_PTS 6000
#define N_TRI 16000
#define N_MOV 4000
#define N_BND 1500
#define BATCH 16
#define EPSF 1e-8f

// GEMM tiling: C[m=4000,n=16] = Vf[m,k=16000] * D[k,16]
#define CK 64                 // k per iteration
#define NCHUNK (N_TRI / CK)   // 250
#define KS 9                  // k-splits: grid 32 x 9 = 288 blocks ~ 2 waves
#define MTILES 32             // 32 * 128 m-rows

// smem layout (dynamic): A stages pitch 288B x 128 rows; B stages pitch 144B x 32 rows
#define A_PITCH 288
#define B_PITCH 144
#define A_STAGE (128 * A_PITCH)   // 36864
#define B_STAGE (32 * B_PITCH)    // 4608
#define OFF_A0 0
#define OFF_A1 A_STAGE
#define OFF_B0 (2 * A_STAGE)
#define OFF_B1 (2 * A_STAGE + B_STAGE)
#define SMEM_BYTES (2 * A_STAGE + 2 * B_STAGE)   // 82944
#define STAGE_TX (128 * 256 + 32 * 128)          // 36864 bytes per stage fill

// ------------------------- device scratch -------------------------
__device__ double g_volc;
__device__ double g_vol[BATCH];
__device__ int    g_owner1[N_PTS];
__device__ int    g_owner2[N_PTS];
__device__ float  g_pz[BATCH * N_PTS * 3];
__device__ __nv_bfloat16 g_dsp[32 * N_TRI];      // rows 0-15: hi[b], rows 16-31: lo[b]
__device__ float  g_cpart[KS * 4096 * 16];       // [ks][m pad 4096][b]
__device__ float  g_c[BATCH * N_MOV];
__device__ float  g_s[BATCH];

// ------------------------- small kernels -------------------------
__global__ void k_init() {
    int i = blockIdx.x * 256 + threadIdx.x;
    if (i < N_PTS) { g_owner1[i] = -1; g_owner2[i] = -1; }
    if (i == 0) g_volc = 0.0;
    if (i < BATCH) g_vol[i] = 0.0;
}

__global__ void k_owners(const int* __restrict__ idx1, const int* __restrict__ idx2) {
    int i = blockIdx.x * 256 + threadIdx.x;
    if (i < N_MOV) atomicMax(&g_owner1[idx1[i]], i);
    if (i < N_BND) atomicMax(&g_owner2[idx2[i]], i);
}

__global__ void k_build(const float* __restrict__ x, const float* __restrict__ y,
                        const float* __restrict__ pz0, float* __restrict__ out) {
    int i = blockIdx.x * 256 + threadIdx.x;
    if (i < BATCH * N_PTS) {
        int b = i / N_PTS, p = i - b * N_PTS;
        float cx = pz0[p * 3 + 0], cy = pz0[p * 3 + 1], cz = pz0[p * 3 + 2];
        int o2 = g_owner2[p];
        if (o2 >= 0) {
            cx = y[b * (2 * N_BND) + o2 * 2 + 0];
            cz = y[b * (2 * N_BND) + o2 * 2 + 1];
        }
        int o1 = g_owner1[p];
        if (o1 >= 0) {
            cx = x[(b * N_MOV + o1) * 3 + 0];
            cy = x[(b * N_MOV + o1) * 3 + 1];
            cz = x[(b * N_MOV + o1) * 3 + 2];
        }
        g_pz[i * 3 + 0] = cx; g_pz[i * 3 + 1] = cy; g_pz[i * 3 + 2] = cz;
    }
    int stride = gridDim.x * 256;
    for (int j = i; j < BATCH * N_MOV * 3; j += stride) out[j] = x[j];
}

__global__ void k_vol(const float* __restrict__ pz0, const int* __restrict__ tri) {
    __shared__ double sred[256];
    int t = blockIdx.x * 256 + threadIdx.x;
    int b = blockIdx.y;
    const float* P = (b < BATCH) ? (g_pz + (size_t)b * N_PTS * 3) : pz0;
    double contrib = 0.0;
    if (t < N_TRI) {
        int p0 = tri[3 * t + 0] * 3, p1 = tri[3 * t + 1] * 3, p2 = tri[3 * t + 2] * 3;
        float x0 = P[p0], y0 = P[p0 + 1], z0 = P[p0 + 2];
        float x1 = P[p1], y1 = P[p1 + 1], z1 = P[p1 + 2];
        float x2 = P[p2], y2 = P[p2 + 1], z2 = P[p2 + 2];
        float det = (y1 - y0) * (z2 - z0) - (z1 - z0) * (y2 - y0);
        contrib = (double)((x0 + x1 + x2) * (det * (1.0f / 6.0f)));
    }
    sred[threadIdx.x] = contrib;
    __syncthreads();
    for (int o = 128; o > 0; o >>= 1) {
        if (threadIdx.x < o) sred[threadIdx.x] += sred[threadIdx.x + o];
        __syncthreads();
    }
    if (threadIdx.x == 0) {
        if (b < BATCH) atomicAdd(&g_vol[b], sred[0]);
        else           atomicAdd(&g_volc, sred[0]);
    }
}

// dets -> bf16 hi/lo planes g_dsp[b][t] (hi) and g_dsp[16+b][t] (lo)
template <int AXIS>
__global__ void k_det(const int* __restrict__ tri) {
    int i = blockIdx.x * 256 + threadIdx.x;
    if (i >= BATCH * N_TRI) return;
    int b = i / N_TRI;
    int t = i - b * N_TRI;
    int p0 = tri[3 * t + 0] * 3, p1 = tri[3 * t + 1] * 3, p2 = tri[3 * t + 2] * 3;
    const float* P = g_pz + (size_t)b * N_PTS * 3;
    float det;
    if (AXIS == 2) {       // coeff_z: (x,y), pivot vertex 2
        float x0 = P[p0], y0 = P[p0 + 1], x1 = P[p1], y1 = P[p1 + 1], x2 = P[p2], y2 = P[p2 + 1];
        det = (x0 - x2) * (y1 - y2) - (y0 - y2) * (x1 - x2);
    } else if (AXIS == 1) { // coeff_y: (x,z), pivot vertex 1
        float x0 = P[p0], z0 = P[p0 + 2], x1 = P[p1], z1 = P[p1 + 2], x2 = P[p2], z2 = P[p2 + 2];
        det = (x0 - x1) * (z2 - z1) - (z0 - z1) * (x2 - x1);
    } else {               // coeff_x: (y,z), pivot vertex 0
        float y0 = P[p0 + 1], z0 = P[p0 + 2], y1 = P[p1 + 1], z1 = P[p1 + 2], y2 = P[p2 + 1], z2 = P[p2 + 2];
        det = (y1 - y0) * (z2 - z0) - (z1 - z0) * (y2 - y0);
    }
    float v = det * (1.0f / 6.0f);
    __nv_bfloat16 h = __float2bfloat16_rn(v);
    __nv_bfloat16 l = __float2bfloat16_rn(v - __bfloat162float(h));
    g_dsp[b * N_TRI + t] = h;
    g_dsp[(16 + b) * N_TRI + t] = l;
}

// ------------------------- helpers -------------------------
__device__ __forceinline__ uint32_t smem_u32(const void* p) {
    return (uint32_t)__cvta_generic_to_shared(p);
}
__device__ __forceinline__ void bulk_g2s(uint32_t dst, const void* src, uint32_t bytes, uint32_t mbar) {
    asm volatile(
        "cp.async.bulk.shared::cluster.global.mbarrier::complete_tx::bytes [%0], [%1], %2, [%3];"
        :: "r"(dst), "l"(src), "r"(bytes), "r"(mbar) : "memory");
}
__device__ __forceinline__ void mbar_wait(uint32_t addr, uint32_t parity) {
    asm volatile(
        "{\n\t.reg .pred P;\n\t"
        "W%=:\n\tmbarrier.try_wait.parity.acquire.cta.shared::cta.b64 P, [%0], %1;\n\t"
        "@!P bra W%=;\n\t}"
        :: "r"(addr), "r"(parity) : "memory");
}
// split float2 -> (hi bf16x2, lo bf16x2); low half = first element
__device__ __forceinline__ void bsplit(float a0, float a1, uint32_t& h, uint32_t& l) {
    asm("cvt.rn.bf16x2.f32 %0, %1, %2;" : "=r"(h) : "f"(a1), "f"(a0));
    float h0 = __uint_as_float(h << 16);
    float h1 = __uint_as_float(h & 0xffff0000u);
    asm("cvt.rn.bf16x2.f32 %0, %1, %2;" : "=r"(l) : "f"(a1 - h1), "f"(a0 - h0));
}
#define MMA16816(C0,C1,C2,C3,A0,A1,A2,A3,B0,B1) \
    asm("mma.sync.aligned.m16n8k16.row.col.f32.bf16.bf16.f32 " \
        "{%0,%1,%2,%3},{%4,%5,%6,%7},{%8,%9},{%0,%1,%2,%3};" \
        : "+f"(C0), "+f"(C1), "+f"(C2), "+f"(C3) \
        : "r"(A0), "r"(A1), "r"(A2), "r"(A3), "r"(B0), "r"(B1))

// ------------------------- GEMM: warp-level bf16 MMA, bulk-async pipelined -------------------------
__global__ void __launch_bounds__(256, 1) k_gemm(const float* __restrict__ Vf) {
    extern __shared__ __align__(128) char sm[];
    __shared__ __align__(8) unsigned long long s_mbar[2];

    const int tid  = threadIdx.x;
    const int lane = tid & 31;
    const int w    = tid >> 5;
    const int g    = lane >> 2;     // 0..7
    const int tig  = lane & 3;      // 0..3
    const int mbase = blockIdx.x * 128;
    const int ksid  = blockIdx.y;
    const int c0 = (NCHUNK * ksid) / KS;
    const int c1 = (NCHUNK * (ksid + 1)) / KS;

    const uint32_t mb[2] = { smem_u32(&s_mbar[0]), smem_u32(&s_mbar[1]) };
    if (tid == 0) {
        asm volatile("mbarrier.init.shared.b64 [%0], 1;" :: "r"(mb[0]) : "memory");
        asm volatile("mbarrier.init.shared.b64 [%0], 1;" :: "r"(mb[1]) : "memory");
        asm volatile("fence.proxy.async.shared::cta;" ::: "memory");
    }
    __syncthreads();

    const uint32_t sbase = smem_u32(sm);
    const uint32_t aoff[2] = { OFF_A0, OFF_A1 };
    const uint32_t boff[2] = { OFF_B0, OFF_B1 };

    // per-thread load roles
    int arow = mbase + tid; if (arow > N_MOV - 1) arow = N_MOV - 1;   // tid<128: Vf row
    const float* asrc = Vf + (size_t)arow * N_TRI;
    const int drow = tid - 128;                                        // 128..159: D row
    const __nv_bfloat16* dsrc = g_dsp + (size_t)(drow < 0 ? 0 : drow) * N_TRI;

    auto issue = [&](int st, int it) {
        const int t0 = it * CK;
        if (tid == 0)
            asm volatile("mbarrier.arrive.expect_tx.shared.b64 _, [%0], %1;"
                         :: "r"(mb[st]), "r"((uint32_t)STAGE_TX) : "memory");
        if (tid < 128)
            bulk_g2s(sbase + aoff[st] + tid * A_PITCH, asrc + t0, 256, mb[st]);
        else if (tid < 160)
            bulk_g2s(sbase + boff[st] + drow * B_PITCH, dsrc + t0, 128, mb[st]);
    };

    const int niter = c1 - c0;
    issue(0, c0);
    if (niter > 1) issue(1, c0 + 1);

    float acc[2][4];
#pragma unroll
    for (int nt = 0; nt < 2; nt++)
#pragma unroll
        for (int q = 0; q < 4; q++) acc[nt][q] = 0.f;

    int phase[2] = { 0, 0 };

    for (int li = 0; li < niter; ++li) {
        const int st = li & 1;
        mbar_wait(mb[st], phase[st]);
        phase[st] ^= 1;

        const char* A0 = sm + aoff[st] + (w * 16 + g) * A_PITCH;   // row g of warp's m16
        const char* A8 = A0 + 8 * A_PITCH;                         // row g+8
        const char* B  = sm + boff[st];

#pragma unroll
        for (int ks = 0; ks < 4; ks++) {
            const int ab = ks * 64 + tig * 8;
            float2 x00 = *reinterpret_cast<const float2*>(A0 + ab);
            float2 x10 = *reinterpret_cast<const float2*>(A8 + ab);
            float2 x01 = *reinterpret_cast<const float2*>(A0 + ab + 32);
            float2 x11 = *reinterpret_cast<const float2*>(A8 + ab + 32);
            uint32_t ah0, al0, ah1, al1, ah2, al2, ah3, al3;
            bsplit(x00.x, x00.y, ah0, al0);
            bsplit(x10.x, x10.y, ah1, al1);
            bsplit(x01.x, x01.y, ah2, al2);
            bsplit(x11.x, x11.y, ah3, al3);

            const int kb = ks * 32 + tig * 4;
            // hi plane rows 0-15, lo plane rows 16-31; n-tile0 rows g.., n-tile1 rows g+8
            uint32_t bh0a = *reinterpret_cast<const uint32_t*>(B + g * B_PITCH + kb);
            uint32_t bh0b = *reinterpret_cast<const uint32_t*>(B + g * B_PITCH + kb + 16);
            uint32_t bh1a = *reinterpret_cast<const uint32_t*>(B + (8 + g) * B_PITCH + kb);
            uint32_t bh1b = *reinterpret_cast<const uint32_t*>(B + (8 + g) * B_PITCH + kb + 16);
            uint32_t bl0a = *reinterpret_cast<const uint32_t*>(B + (16 + g) * B_PITCH + kb);
            uint32_t bl0b = *reinterpret_cast<const uint32_t*>(B + (16 + g) * B_PITCH + kb + 16);
            uint32_t bl1a = *reinterpret_cast<const uint32_t*>(B + (24 + g) * B_PITCH + kb);
            uint32_t bl1b = *reinterpret_cast<const uint32_t*>(B + (24 + g) * B_PITCH + kb + 16);

            MMA16816(acc[0][0], acc[0][1], acc[0][2], acc[0][3], ah0, ah1, ah2, ah3, bh0a, bh0b);
            MMA16816(acc[0][0], acc[0][1], acc[0][2], acc[0][3], ah0, ah1, ah2, ah3, bl0a, bl0b);
            MMA16816(acc[0][0], acc[0][1], acc[0][2], acc[0][3], al0, al1, al2, al3, bh0a, bh0b);
            MMA16816(acc[1][0], acc[1][1], acc[1][2], acc[1][3], ah0, ah1, ah2, ah3, bh1a, bh1b);
            MMA16816(acc[1][0], acc[1][1], acc[1][2], acc[1][3], ah0, ah1, ah2, ah3, bl1a, bl1b);
            MMA16816(acc[1][0], acc[1][1], acc[1][2], acc[1][3], al0, al1, al2, al3, bh1a, bh1b);
        }

        __syncthreads();                 // all warps done reading stage st
        if (li + 2 < niter) issue(st, c0 + li + 2);
    }

    // epilogue: d0,d1 -> (row g, cols 2*tig, 2*tig+1); d2,d3 -> row g+8
    const int m0 = mbase + w * 16 + g;
    const int m1 = m0 + 8;
#pragma unroll
    for (int nt = 0; nt < 2; nt++) {
        const int n0 = nt * 8 + tig * 2;
        if (m0 < N_MOV)
            *reinterpret_cast<float2*>(&g_cpart[((size_t)ksid * 4096 + m0) * 16 + n0]) =
                make_float2(acc[nt][0], acc[nt][1]);
        if (m1 < N_MOV)
            *reinterpret_cast<float2*>(&g_cpart[((size_t)ksid * 4096 + m1) * 16 + n0]) =
                make_float2(acc[nt][2], acc[nt][3]);
    }
}

// ------------------------- finalize c, per-batch scale -------------------------
__global__ void k_scale() {
    __shared__ float red[256];
    int b = blockIdx.x;
    int tid = threadIdx.x;
    float sq = 0.f;
    for (int m = tid; m < N_MOV; m += 256) {
        float cv = 0.f;
#pragma unroll
        for (int sp = 0; sp < KS; sp++)
            cv += g_cpart[((size_t)sp * 4096 + m) * 16 + b];
        g_c[b * N_MOV + m] = cv;
        sq += cv * cv;
    }
    red[tid] = sq;
    __syncthreads();
    for (int o = 128; o > 0; o >>= 1) {
        if (tid < o) red[tid] += red[tid + o];
        __syncthreads();
    }
    if (tid == 0) {
        float a = (float)((g_volc - g_vol[b]) / 3.0);
        g_s[b] = a / (red[0] + EPSF);
    }
}

__global__ void k_update(const int* __restrict__ idx1, float* __restrict__ out, int axis) {
    int i = blockIdx.x * 256 + threadIdx.x;
    if (i >= BATCH * N_MOV) return;
    int b = i / N_MOV;
    int m = i - b * N_MOV;
    float nv = out[i * 3 + axis] + g_c[i] * g_s[b];
    out[i * 3 + axis] = nv;
    int p = idx1[m];
    if (g_owner1[p] == m) g_pz[((size_t)b * N_PTS + p) * 3 + axis] = nv;
}

// ------------------------- host -------------------------
extern "C" void kernel_launch(void* const* d_in, const int* in_sizes, int n_in,
                              void* d_out, int out_size) {
    const float* x   = (const float*)d_in[0];
    const float* y   = (const float*)d_in[1];
    const float* pz0 = (const float*)d_in[2];
    const float* Vf  = (const float*)d_in[3];
    const int* idx1  = (const int*)d_in[4];
    const int* idx2  = (const int*)d_in[5];
    const int* tri   = (const int*)d_in[6];
    float* out = (float*)d_out;

    static bool attr_set = false;   // idempotent attribute set, not result-affecting state
    if (!attr_set) {
        cudaFuncSetAttribute(k_gemm, cudaFuncAttributeMaxDynamicSharedMemorySize, SMEM_BYTES);
        attr_set = true;
    }

    k_init<<<24, 256>>>();
    k_owners<<<16, 256>>>(idx1, idx2);
    k_build<<<375, 256>>>(x, y, pz0, out);
    k_vol<<<dim3(63, BATCH + 1), 256>>>(pz0, tri);

    k_det<2><<<1000, 256>>>(tri);
    k_gemm<<<dim3(MTILES, KS), 256, SMEM_BYTES>>>(Vf);
    k_scale<<<BATCH, 256>>>();
    k_update<<<250, 256>>>(idx1, out, 2);

    k_det<1><<<1000, 256>>>(tri);
    k_gemm<<<dim3(MTILES, KS), 256, SMEM_BYTES>>>(Vf);
    k_scale<<<BATCH, 256>>>();
    k_update<<<250, 256>>>(idx1, out, 1);

    k_det<0><<<1000, 256>>>(tri);
    k_gemm<<<dim3(MTILES, KS), 256, SMEM_BYTES>>>(Vf);
    k_scale<<<BATCH, 256>>>();
    k_update<<<250, 256>>>(idx1, out, 0);
}